// round 1
// baseline (speedup 1.0000x reference)
#include <cuda_runtime.h>

#define S_LEN 1024
#define CDIM 512
#define NH 8
#define DK 64
#define BDIM 4
#define L2E 1.4426950408889634f

// Scratch (static __device__ arrays per harness rules)
__device__ float g_Q[BDIM * NH * S_LEN * DK];
__device__ float g_K[BDIM * NH * S_LEN * DK];
__device__ float g_V[BDIM * NH * S_LEN * DK];
__device__ float g_res[BDIM * S_LEN * CDIM];

// ---------------------------------------------------------------------------
// Kernel 1: QKV projection.  qkv[b,i,j] = sum_c x[b,c,i] * Wp[j,c] + bp[j]
// Scatter into g_Q/g_K/g_V with layout [b][h][i][d].
// ---------------------------------------------------------------------------
__global__ __launch_bounds__(256) void qkv_kernel(const float* __restrict__ x,
                                                  const float* __restrict__ Wp,
                                                  const float* __restrict__ bp) {
    __shared__ float As[32][65];  // As[kk][ii] = x[b][c0+kk][i0+ii]
    __shared__ float Bs[32][65];  // Bs[kk][jj] = Wp[j0+jj][c0+kk]
    int b  = blockIdx.z;
    int i0 = blockIdx.x * 64;
    int j0 = blockIdx.y * 64;
    int tid = threadIdx.x;
    int tx = tid & 15, ty = tid >> 4;
    float acc[4][4] = {};
    const float* xb = x + (size_t)b * CDIM * S_LEN;

    for (int c0 = 0; c0 < CDIM; c0 += 32) {
        int ii = tid & 63, kk4 = tid >> 6;
        #pragma unroll
        for (int r = 0; r < 8; r++)
            As[kk4 + r * 4][ii] = xb[(size_t)(c0 + kk4 + r * 4) * S_LEN + i0 + ii];
        int kb = tid & 31, jj = tid >> 5;
        #pragma unroll
        for (int r = 0; r < 8; r++)
            Bs[kb][jj + r * 8] = Wp[(size_t)(j0 + jj + r * 8) * CDIM + c0 + kb];
        __syncthreads();
        #pragma unroll
        for (int kk = 0; kk < 32; kk++) {
            float a[4], w[4];
            #pragma unroll
            for (int e = 0; e < 4; e++) { a[e] = As[kk][ty * 4 + e]; w[e] = Bs[kk][tx * 4 + e]; }
            #pragma unroll
            for (int ei = 0; ei < 4; ei++)
                #pragma unroll
                for (int ej = 0; ej < 4; ej++)
                    acc[ei][ej] = fmaf(a[ei], w[ej], acc[ei][ej]);
        }
        __syncthreads();
    }

    #pragma unroll
    for (int ei = 0; ei < 4; ei++) {
        int i = i0 + ty * 4 + ei;
        #pragma unroll
        for (int ej = 0; ej < 4; ej++) {
            int j = j0 + tx * 4 + ej;
            float v = acc[ei][ej] + bp[j];
            int h = j / 192, e = j % 192;
            float* dst = (e < DK) ? g_Q : (e < 2 * DK ? g_K : g_V);
            int d = e & 63;
            dst[(((size_t)b * NH + h) * S_LEN + i) * DK + d] = v;
        }
    }
}

// ---------------------------------------------------------------------------
// Kernel 2: attention, one block per (b,h, 64-query tile).
// Online softmax over 16 key tiles of 64. O accumulators in registers.
// ---------------------------------------------------------------------------
__global__ __launch_bounds__(256) void attn_kernel() {
    extern __shared__ float sm[];
    float* Qs  = sm;               // [64][65]  Qs[d*65+qi], pre-scaled by 1/8
    float* Ks  = Qs + 64 * 65;     // [64][65]  Ks[d*65+kj]
    float* Vs  = Ks + 64 * 65;     // [64][65]  Vs[kj*65+d]
    float* Ss  = Vs + 64 * 65;     // [64][65]  Ss[qi*65+kj]
    float* m_s = Ss + 64 * 65;     // [64]
    float* l_s = m_s + 64;         // [64]
    float* f_s = l_s + 64;         // [64]

    int bh = blockIdx.y;
    int i0 = blockIdx.x * 64;
    const float* Qp = g_Q + (size_t)bh * S_LEN * DK;
    const float* Kp = g_K + (size_t)bh * S_LEN * DK;
    const float* Vp = g_V + (size_t)bh * S_LEN * DK;
    int tid = threadIdx.x;
    int tx = tid & 15, ty = tid >> 4;

    {
        int d = tid & 63, q = tid >> 6;
        #pragma unroll
        for (int r = 0; r < 16; r++)
            Qs[d * 65 + q + r * 4] = Qp[(size_t)(i0 + q + r * 4) * DK + d] * 0.125f;
    }
    if (tid < 64) { m_s[tid] = -1e30f; l_s[tid] = 0.f; }
    float o[4][4] = {};
    __syncthreads();

    for (int j0t = 0; j0t < S_LEN; j0t += 64) {
        {
            int d = tid & 63, q = tid >> 6;
            #pragma unroll
            for (int r = 0; r < 16; r++) {
                int j = q + r * 4;
                float kv = Kp[(size_t)(j0t + j) * DK + d];
                float vv = Vp[(size_t)(j0t + j) * DK + d];
                Ks[d * 65 + j] = kv;
                Vs[j * 65 + d] = vv;
            }
        }
        __syncthreads();

        // S = (Q*scale) K^T  -> registers, then smem
        float s[4][4] = {};
        #pragma unroll
        for (int d = 0; d < 64; d++) {
            float qf[4], kf[4];
            #pragma unroll
            for (int e = 0; e < 4; e++) {
                qf[e] = Qs[d * 65 + ty * 4 + e];
                kf[e] = Ks[d * 65 + tx * 4 + e];
            }
            #pragma unroll
            for (int ei = 0; ei < 4; ei++)
                #pragma unroll
                for (int ej = 0; ej < 4; ej++)
                    s[ei][ej] = fmaf(qf[ei], kf[ej], s[ei][ej]);
        }
        #pragma unroll
        for (int ei = 0; ei < 4; ei++)
            #pragma unroll
            for (int ej = 0; ej < 4; ej++)
                Ss[(ty * 4 + ei) * 65 + tx * 4 + ej] = s[ei][ej];
        __syncthreads();

        // per-row running max + rescale factor
        if (tid < 64) {
            float mx = -1e30f;
            #pragma unroll 8
            for (int j = 0; j < 64; j++) mx = fmaxf(mx, Ss[tid * 65 + j]);
            float mo = m_s[tid];
            float mn = fmaxf(mo, mx);
            m_s[tid] = mn;
            f_s[tid] = exp2f((mo - mn) * L2E);
        }
        __syncthreads();

        // exponentiate own elements, rescale own O rows
        #pragma unroll
        for (int ei = 0; ei < 4; ei++) {
            int r = ty * 4 + ei;
            float mnl = m_s[r] * L2E;
            float fr = f_s[r];
            #pragma unroll
            for (int ej = 0; ej < 4; ej++) {
                float p = exp2f(fmaf(s[ei][ej], L2E, -mnl));
                Ss[r * 65 + tx * 4 + ej] = p;
            }
            #pragma unroll
            for (int ed = 0; ed < 4; ed++) o[ei][ed] *= fr;
        }
        __syncthreads();

        // running denominator
        if (tid < 64) {
            float sum = 0.f;
            #pragma unroll 8
            for (int j = 0; j < 64; j++) sum += Ss[tid * 65 + j];
            l_s[tid] = l_s[tid] * f_s[tid] + sum;
        }

        // O += P V
        #pragma unroll
        for (int kj = 0; kj < 64; kj++) {
            float pf[4], vf[4];
            #pragma unroll
            for (int e = 0; e < 4; e++) {
                pf[e] = Ss[(ty * 4 + e) * 65 + kj];
                vf[e] = Vs[kj * 65 + tx * 4 + e];
            }
            #pragma unroll
            for (int ei = 0; ei < 4; ei++)
                #pragma unroll
                for (int ed = 0; ed < 4; ed++)
                    o[ei][ed] = fmaf(pf[ei], vf[ed], o[ei][ed]);
        }
        __syncthreads();
    }

    int b = bh >> 3, h = bh & 7;
    #pragma unroll
    for (int ei = 0; ei < 4; ei++) {
        int i = i0 + ty * 4 + ei;
        float inv = 1.f / l_s[ty * 4 + ei];
        #pragma unroll
        for (int ed = 0; ed < 4; ed++) {
            int d = tx * 4 + ed;
            g_res[((size_t)b * S_LEN + i) * CDIM + h * DK + d] = o[ei][ed] * inv;
        }
    }
}

// ---------------------------------------------------------------------------
// Kernel 3: out[b,c,i] = sum_f res[b,i,f] * Wo[c,f] + bo[c] + x[b,c,i]
// ---------------------------------------------------------------------------
__global__ __launch_bounds__(256) void proj_kernel(const float* __restrict__ x,
                                                   const float* __restrict__ Wo,
                                                   const float* __restrict__ bo,
                                                   float* __restrict__ out) {
    __shared__ float As[32][65];  // [f][i]
    __shared__ float Bs[32][65];  // [f][c]
    int b  = blockIdx.z;
    int i0 = blockIdx.x * 64;
    int c0 = blockIdx.y * 64;
    int tid = threadIdx.x;
    int tx = tid & 15, ty = tid >> 4;
    float acc[4][4] = {};  // [ec][ei]
    const float* resb = g_res + (size_t)b * S_LEN * CDIM;

    for (int f0 = 0; f0 < CDIM; f0 += 32) {
        int f = tid & 31, rr = tid >> 5;
        #pragma unroll
        for (int r = 0; r < 8; r++)
            As[f][rr + r * 8] = resb[(size_t)(i0 + rr + r * 8) * CDIM + f0 + f];
        #pragma unroll
        for (int r = 0; r < 8; r++)
            Bs[f][rr + r * 8] = Wo[(size_t)(c0 + rr + r * 8) * CDIM + f0 + f];
        __syncthreads();
        #pragma unroll
        for (int kk = 0; kk < 32; kk++) {
            float af[4], bf[4];
            #pragma unroll
            for (int e = 0; e < 4; e++) { af[e] = As[kk][tx * 4 + e]; bf[e] = Bs[kk][ty * 4 + e]; }
            #pragma unroll
            for (int ec = 0; ec < 4; ec++)
                #pragma unroll
                for (int ei = 0; ei < 4; ei++)
                    acc[ec][ei] = fmaf(bf[ec], af[ei], acc[ec][ei]);
        }
        __syncthreads();
    }

    #pragma unroll
    for (int ec = 0; ec < 4; ec++) {
        int c = c0 + ty * 4 + ec;
        float bias = bo[c];
        #pragma unroll
        for (int ei = 0; ei < 4; ei++) {
            int i = i0 + tx * 4 + ei;
            size_t idx = ((size_t)b * CDIM + c) * S_LEN + i;
            out[idx] = acc[ec][ei] + bias + x[idx];
        }
    }
}

// ---------------------------------------------------------------------------
extern "C" void kernel_launch(void* const* d_in, const int* in_sizes, int n_in,
                              void* d_out, int out_size) {
    const float* x  = (const float*)d_in[0];
    const float* Wp = (const float*)d_in[1];
    const float* bp = (const float*)d_in[2];
    const float* Wo = (const float*)d_in[3];
    const float* bo = (const float*)d_in[4];
    float* out = (float*)d_out;

    const int attn_smem = (4 * 64 * 65 + 3 * 64) * sizeof(float);  // 67328 B
    cudaFuncSetAttribute(attn_kernel, cudaFuncAttributeMaxDynamicSharedMemorySize, attn_smem);

    qkv_kernel<<<dim3(S_LEN / 64, 1536 / 64, BDIM), 256>>>(x, Wp, bp);
    attn_kernel<<<dim3(S_LEN / 64, BDIM * NH), 256, attn_smem>>>();
    proj_kernel<<<dim3(S_LEN / 64, CDIM / 64, BDIM), 256>>>(x, Wo, bo, out);
}

// round 2
// speedup vs baseline: 3.6783x; 3.6783x over previous
#include <cuda_runtime.h>

#define S_LEN 1024
#define CDIM 512
#define NH 8
#define DK 64
#define BDIM 4
#define L2E 1.4426950408889634f

// Scratch (static __device__ arrays per harness rules)
__device__ float g_Q[BDIM * NH * S_LEN * DK];
__device__ float g_K[BDIM * NH * S_LEN * DK];
__device__ float g_V[BDIM * NH * S_LEN * DK];
__device__ float g_res[BDIM * S_LEN * CDIM];

// ---------------------------------------------------------------------------
// tf32 helpers
// ---------------------------------------------------------------------------
__device__ __forceinline__ unsigned f2tf(float f) {
    unsigned u;
    asm("cvt.rna.tf32.f32 %0, %1;" : "=r"(u) : "f"(f));
    return u;
}
__device__ __forceinline__ uint4 f2tf4(float4 v) {
    uint4 u;
    u.x = f2tf(v.x); u.y = f2tf(v.y); u.z = f2tf(v.z); u.w = f2tf(v.w);
    return u;
}
// D = A(16x8) * B(8x8) + C,  tf32 inputs, f32 accumulate.  d may alias c.
__device__ __forceinline__ void mma_tf32(float* d, const unsigned* a,
                                         const unsigned* b, const float* c) {
    asm volatile(
        "mma.sync.aligned.m16n8k8.row.col.f32.tf32.tf32.f32 "
        "{%0,%1,%2,%3},{%4,%5,%6,%7},{%8,%9},{%10,%11,%12,%13};"
        : "=f"(d[0]), "=f"(d[1]), "=f"(d[2]), "=f"(d[3])
        : "r"(a[0]), "r"(a[1]), "r"(a[2]), "r"(a[3]),
          "r"(b[0]), "r"(b[1]),
          "f"(c[0]), "f"(c[1]), "f"(c[2]), "f"(c[3]));
}

// ---------------------------------------------------------------------------
// Kernel 1: QKV projection.  qkv[b,i,j] = sum_c x[b,c,i]*Wp[j,c] + bp[j]
// M=i (128/block), N=j (128/block), K=c (512, chunks of 32).
// ---------------------------------------------------------------------------
__global__ __launch_bounds__(256) void qkv_kernel(const float* __restrict__ x,
                                                  const float* __restrict__ Wp,
                                                  const float* __restrict__ bp) {
    __shared__ unsigned As[32][136];  // [k][m] tf32
    __shared__ unsigned Bs[128][36];  // [n][k] tf32
    int b  = blockIdx.z;
    int i0 = blockIdx.x * 128;
    int j0 = blockIdx.y * 128;
    int tid = threadIdx.x;
    int lane = tid & 31, warp = tid >> 5;
    int wm = warp >> 1, wn = warp & 1;
    int group = lane >> 2, tig = lane & 3;
    const float* xb = x + (size_t)b * CDIM * S_LEN;

    float acc[2][8][4] = {};

    for (int c0 = 0; c0 < CDIM; c0 += 32) {
        {   // A: 32 k-rows x 128 m, coalesced along m
            int kk = tid >> 3, mv = tid & 7;
            #pragma unroll
            for (int r = 0; r < 4; r++) {
                int m4 = (mv + 8 * r) * 4;
                float4 v = *(const float4*)&xb[(size_t)(c0 + kk) * S_LEN + i0 + m4];
                *(uint4*)&As[kk][m4] = f2tf4(v);
            }
        }
        {   // B: 128 n-rows x 32 k, coalesced along k
            int t = tid & 7, nb = tid >> 3;
            #pragma unroll
            for (int r = 0; r < 4; r++) {
                int nn = nb + 32 * r;
                float4 v = *(const float4*)&Wp[(size_t)(j0 + nn) * CDIM + c0 + 4 * t];
                *(uint4*)&Bs[nn][4 * t] = f2tf4(v);
            }
        }
        __syncthreads();

        #pragma unroll
        for (int kf = 0; kf < 4; kf++) {
            int k0 = kf * 8;
            unsigned a[2][4], bf[8][2];
            #pragma unroll
            for (int mi = 0; mi < 2; mi++) {
                int m = wm * 32 + mi * 16 + group;
                a[mi][0] = As[k0 + tig][m];
                a[mi][1] = As[k0 + tig][m + 8];
                a[mi][2] = As[k0 + tig + 4][m];
                a[mi][3] = As[k0 + tig + 4][m + 8];
            }
            #pragma unroll
            for (int nf = 0; nf < 8; nf++) {
                int n = wn * 64 + nf * 8 + group;
                bf[nf][0] = Bs[n][k0 + tig];
                bf[nf][1] = Bs[n][k0 + tig + 4];
            }
            #pragma unroll
            for (int mi = 0; mi < 2; mi++)
                #pragma unroll
                for (int nf = 0; nf < 8; nf++)
                    mma_tf32(acc[mi][nf], a[mi], bf[nf], acc[mi][nf]);
        }
        __syncthreads();
    }

    // Epilogue: scatter into g_Q/g_K/g_V, layout [b][h][i][d]
    #pragma unroll
    for (int mi = 0; mi < 2; mi++) {
        int ir = i0 + wm * 32 + mi * 16 + group;
        #pragma unroll
        for (int nf = 0; nf < 8; nf++) {
            int jc = j0 + wn * 64 + nf * 8 + 2 * tig;
            #pragma unroll
            for (int e = 0; e < 4; e++) {
                int i = ir + (e >> 1) * 8;
                int j = jc + (e & 1);
                float v = acc[mi][nf][e] + bp[j];
                int h = j / 192, rem = j - h * 192;
                float* dst = (rem < DK) ? g_Q : (rem < 2 * DK ? g_K : g_V);
                int d = rem & 63;
                dst[(((size_t)b * NH + h) * S_LEN + i) * DK + d] = v;
            }
        }
    }
}

// ---------------------------------------------------------------------------
// Kernel 2: flash attention. Block = (128-query tile, bh). 8 warps x m16.
// Q fragments in registers; K/V staged in smem (natural layout);
// P kept in registers, C-frag -> A-frag via quad shuffles.
// ---------------------------------------------------------------------------
__global__ __launch_bounds__(256) void attn_kernel() {
    __shared__ unsigned Ks[64][68];  // [key][d] tf32
    __shared__ unsigned Vs[64][72];  // [key][d] tf32
    int bh = blockIdx.y;
    int i0 = blockIdx.x * 128;
    int tid = threadIdx.x;
    int lane = tid & 31, warp = tid >> 5;
    int group = lane >> 2, tig = lane & 3;
    const float* Qp = g_Q + (size_t)bh * S_LEN * DK;
    const float* Kp = g_K + (size_t)bh * S_LEN * DK;
    const float* Vp = g_V + (size_t)bh * S_LEN * DK;

    // Q fragments (pre-scaled by 1/8), persistent
    unsigned qa[8][4];
    int r0 = i0 + warp * 16 + group, r1 = r0 + 8;
    #pragma unroll
    for (int kf = 0; kf < 8; kf++) {
        int d0 = kf * 8 + tig;
        qa[kf][0] = f2tf(Qp[(size_t)r0 * DK + d0] * 0.125f);
        qa[kf][1] = f2tf(Qp[(size_t)r1 * DK + d0] * 0.125f);
        qa[kf][2] = f2tf(Qp[(size_t)r0 * DK + d0 + 4] * 0.125f);
        qa[kf][3] = f2tf(Qp[(size_t)r1 * DK + d0 + 4] * 0.125f);
    }

    float o[8][4] = {};
    float mrun0 = -1e30f, mrun1 = -1e30f;
    float lrun0 = 0.f, lrun1 = 0.f;

    for (int jt = 0; jt < S_LEN; jt += 64) {
        __syncthreads();  // previous iteration done with Ks/Vs
        {
            int key = tid >> 4, dv = (tid & 15) * 4;
            #pragma unroll
            for (int r = 0; r < 4; r++) {
                int kk = key + 16 * r;
                float4 kv = *(const float4*)&Kp[(size_t)(jt + kk) * DK + dv];
                float4 vv = *(const float4*)&Vp[(size_t)(jt + kk) * DK + dv];
                *(uint4*)&Ks[kk][dv] = f2tf4(kv);
                *(uint4*)&Vs[kk][dv] = f2tf4(vv);
            }
        }
        __syncthreads();

        // S = Q K^T : m16 x n64, k=64
        float s[8][4] = {};
        #pragma unroll
        for (int kf = 0; kf < 8; kf++) {
            int k0 = kf * 8;
            #pragma unroll
            for (int nf = 0; nf < 8; nf++) {
                unsigned bf[2];
                bf[0] = Ks[nf * 8 + group][k0 + tig];
                bf[1] = Ks[nf * 8 + group][k0 + tig + 4];
                mma_tf32(s[nf], qa[kf], bf, s[nf]);
            }
        }

        // row max over this key tile
        float mx0 = -1e30f, mx1 = -1e30f;
        #pragma unroll
        for (int nf = 0; nf < 8; nf++) {
            mx0 = fmaxf(mx0, fmaxf(s[nf][0], s[nf][1]));
            mx1 = fmaxf(mx1, fmaxf(s[nf][2], s[nf][3]));
        }
        mx0 = fmaxf(mx0, __shfl_xor_sync(0xffffffffu, mx0, 1));
        mx0 = fmaxf(mx0, __shfl_xor_sync(0xffffffffu, mx0, 2));
        mx1 = fmaxf(mx1, __shfl_xor_sync(0xffffffffu, mx1, 1));
        mx1 = fmaxf(mx1, __shfl_xor_sync(0xffffffffu, mx1, 2));

        float mn0 = fmaxf(mrun0, mx0), mn1 = fmaxf(mrun1, mx1);
        float f0 = exp2f((mrun0 - mn0) * L2E);
        float f1 = exp2f((mrun1 - mn1) * L2E);
        mrun0 = mn0; mrun1 = mn1;
        float ml0 = mn0 * L2E, ml1 = mn1 * L2E;

        // exponentiate (convert to tf32 in place), accumulate denominators
        unsigned p[8][4];
        float sum0 = 0.f, sum1 = 0.f;
        #pragma unroll
        for (int nf = 0; nf < 8; nf++) {
            float p0 = exp2f(fmaf(s[nf][0], L2E, -ml0));
            float p1 = exp2f(fmaf(s[nf][1], L2E, -ml0));
            float p2 = exp2f(fmaf(s[nf][2], L2E, -ml1));
            float p3 = exp2f(fmaf(s[nf][3], L2E, -ml1));
            sum0 += p0 + p1; sum1 += p2 + p3;
            p[nf][0] = f2tf(p0); p[nf][1] = f2tf(p1);
            p[nf][2] = f2tf(p2); p[nf][3] = f2tf(p3);
        }
        sum0 += __shfl_xor_sync(0xffffffffu, sum0, 1);
        sum0 += __shfl_xor_sync(0xffffffffu, sum0, 2);
        sum1 += __shfl_xor_sync(0xffffffffu, sum1, 1);
        sum1 += __shfl_xor_sync(0xffffffffu, sum1, 2);
        lrun0 = lrun0 * f0 + sum0;
        lrun1 = lrun1 * f1 + sum1;

        // rescale O
        #pragma unroll
        for (int nf = 0; nf < 8; nf++) {
            o[nf][0] *= f0; o[nf][1] *= f0;
            o[nf][2] *= f1; o[nf][3] *= f1;
        }

        // O += P V : A-frags built from P C-frags via quad shuffles
        int src1 = (lane & ~3) | (tig >> 1);
        int src2 = src1 + 2;
        bool odd = (tig & 1);
        #pragma unroll
        for (int kf = 0; kf < 8; kf++) {
            unsigned s00 = __shfl_sync(0xffffffffu, p[kf][0], src1);
            unsigned s01 = __shfl_sync(0xffffffffu, p[kf][1], src1);
            unsigned s02 = __shfl_sync(0xffffffffu, p[kf][2], src1);
            unsigned s03 = __shfl_sync(0xffffffffu, p[kf][3], src1);
            unsigned t00 = __shfl_sync(0xffffffffu, p[kf][0], src2);
            unsigned t01 = __shfl_sync(0xffffffffu, p[kf][1], src2);
            unsigned t02 = __shfl_sync(0xffffffffu, p[kf][2], src2);
            unsigned t03 = __shfl_sync(0xffffffffu, p[kf][3], src2);
            unsigned a[4];
            a[0] = odd ? s01 : s00;
            a[1] = odd ? s03 : s02;
            a[2] = odd ? t01 : t00;
            a[3] = odd ? t03 : t02;
            int k0 = kf * 8;
            #pragma unroll
            for (int nf = 0; nf < 8; nf++) {
                unsigned bf[2];
                bf[0] = Vs[k0 + tig][nf * 8 + group];
                bf[1] = Vs[k0 + tig + 4][nf * 8 + group];
                mma_tf32(o[nf], a, bf, o[nf]);
            }
        }
    }

    // Epilogue -> g_res[b][i][h*64+d]
    int b = bh >> 3, h = bh & 7;
    float inv0 = 1.f / lrun0, inv1 = 1.f / lrun1;
    #pragma unroll
    for (int nf = 0; nf < 8; nf++) {
        int d = h * DK + nf * 8 + 2 * tig;
        float2 v0 = make_float2(o[nf][0] * inv0, o[nf][1] * inv0);
        float2 v1 = make_float2(o[nf][2] * inv1, o[nf][3] * inv1);
        *(float2*)&g_res[((size_t)b * S_LEN + r0) * CDIM + d] = v0;
        *(float2*)&g_res[((size_t)b * S_LEN + r1) * CDIM + d] = v1;
    }
}

// ---------------------------------------------------------------------------
// Kernel 3: out[b,c,i] = sum_f res[b,i,f]*Wo[c,f] + bo[c] + x[b,c,i]
// M=c (128/block), N=i (128/block), K=f (512, chunks of 32).
// ---------------------------------------------------------------------------
__global__ __launch_bounds__(256) void proj_kernel(const float* __restrict__ x,
                                                   const float* __restrict__ Wo,
                                                   const float* __restrict__ bo,
                                                   float* __restrict__ out) {
    __shared__ unsigned As[128][36];  // [c][f] tf32
    __shared__ unsigned Bs[128][36];  // [i][f] tf32
    int b  = blockIdx.z;
    int i0 = blockIdx.x * 128;
    int c0 = blockIdx.y * 128;
    int tid = threadIdx.x;
    int lane = tid & 31, warp = tid >> 5;
    int wm = warp >> 1, wn = warp & 1;
    int group = lane >> 2, tig = lane & 3;
    const float* resb = g_res + (size_t)b * S_LEN * CDIM;

    float acc[2][8][4] = {};

    for (int f0 = 0; f0 < CDIM; f0 += 32) {
        int t = tid & 7, rb = tid >> 3;
        #pragma unroll
        for (int r = 0; r < 4; r++) {
            int rr = rb + 32 * r;
            float4 av = *(const float4*)&Wo[(size_t)(c0 + rr) * CDIM + f0 + 4 * t];
            float4 bv = *(const float4*)&resb[(size_t)(i0 + rr) * CDIM + f0 + 4 * t];
            *(uint4*)&As[rr][4 * t] = f2tf4(av);
            *(uint4*)&Bs[rr][4 * t] = f2tf4(bv);
        }
        __syncthreads();

        #pragma unroll
        for (int kf = 0; kf < 4; kf++) {
            int k0 = kf * 8;
            unsigned a[2][4], bf[8][2];
            #pragma unroll
            for (int mi = 0; mi < 2; mi++) {
                int m = wm * 32 + mi * 16 + group;
                a[mi][0] = As[m][k0 + tig];
                a[mi][1] = As[m + 8][k0 + tig];
                a[mi][2] = As[m][k0 + tig + 4];
                a[mi][3] = As[m + 8][k0 + tig + 4];
            }
            #pragma unroll
            for (int nf = 0; nf < 8; nf++) {
                int n = wn * 64 + nf * 8 + group;
                bf[nf][0] = Bs[n][k0 + tig];
                bf[nf][1] = Bs[n][k0 + tig + 4];
            }
            #pragma unroll
            for (int mi = 0; mi < 2; mi++)
                #pragma unroll
                for (int nf = 0; nf < 8; nf++)
                    mma_tf32(acc[mi][nf], a[mi], bf[nf], acc[mi][nf]);
        }
        __syncthreads();
    }

    // Epilogue: bias + residual, coalesced along i
    #pragma unroll
    for (int mi = 0; mi < 2; mi++) {
        int cr = c0 + wm * 32 + mi * 16 + group;
        #pragma unroll
        for (int nf = 0; nf < 8; nf++) {
            int ic = i0 + wn * 64 + nf * 8 + 2 * tig;
            #pragma unroll
            for (int half = 0; half < 2; half++) {
                int c = cr + half * 8;
                size_t idx = ((size_t)b * CDIM + c) * S_LEN + ic;
                float2 xv = *(const float2*)&x[idx];
                float bias = bo[c];
                float2 ov;
                ov.x = acc[mi][nf][half * 2 + 0] + bias + xv.x;
                ov.y = acc[mi][nf][half * 2 + 1] + bias + xv.y;
                *(float2*)&out[idx] = ov;
            }
        }
    }
}

// ---------------------------------------------------------------------------
extern "C" void kernel_launch(void* const* d_in, const int* in_sizes, int n_in,
                              void* d_out, int out_size) {
    const float* x  = (const float*)d_in[0];
    const float* Wp = (const float*)d_in[1];
    const float* bp = (const float*)d_in[2];
    const float* Wo = (const float*)d_in[3];
    const float* bo = (const float*)d_in[4];
    float* out = (float*)d_out;

    qkv_kernel<<<dim3(S_LEN / 128, 1536 / 128, BDIM), 256>>>(x, Wp, bp);
    attn_kernel<<<dim3(S_LEN / 128, BDIM * NH), 256>>>();
    proj_kernel<<<dim3(S_LEN / 128, CDIM / 128, BDIM), 256>>>(x, Wo, bo, out);
}

// round 3
// speedup vs baseline: 3.8674x; 1.0514x over previous
#include <cuda_runtime.h>

#define S_LEN 1024
#define CDIM 512
#define NH 8
#define DK 64
#define BDIM 4
#define L2E 1.4426950408889634f

// Scratch (static __device__ arrays per harness rules)
__device__ float g_Q[BDIM * NH * S_LEN * DK];
__device__ float g_K[BDIM * NH * S_LEN * DK];
__device__ float g_V[BDIM * NH * S_LEN * DK];
__device__ float g_res[BDIM * S_LEN * CDIM];

// ---------------------------------------------------------------------------
// tf32 helpers
// ---------------------------------------------------------------------------
__device__ __forceinline__ unsigned f2tf(float f) {
    unsigned u;
    asm("cvt.rna.tf32.f32 %0, %1;" : "=r"(u) : "f"(f));
    return u;
}
__device__ __forceinline__ uint4 f2tf4(float4 v) {
    uint4 u;
    u.x = f2tf(v.x); u.y = f2tf(v.y); u.z = f2tf(v.z); u.w = f2tf(v.w);
    return u;
}
// D = A(16x8) * B(8x8) + C,  tf32 inputs, f32 accumulate.  d may alias c.
__device__ __forceinline__ void mma_tf32(float* d, const unsigned* a,
                                         const unsigned* b, const float* c) {
    asm volatile(
        "mma.sync.aligned.m16n8k8.row.col.f32.tf32.tf32.f32 "
        "{%0,%1,%2,%3},{%4,%5,%6,%7},{%8,%9},{%10,%11,%12,%13};"
        : "=f"(d[0]), "=f"(d[1]), "=f"(d[2]), "=f"(d[3])
        : "r"(a[0]), "r"(a[1]), "r"(a[2]), "r"(a[3]),
          "r"(b[0]), "r"(b[1]),
          "f"(c[0]), "f"(c[1]), "f"(c[2]), "f"(c[3]));
}

// ---------------------------------------------------------------------------
// Kernel 1: QKV projection.  qkv[b,i,j] = sum_c x[b,c,i]*Wp[j,c] + bp[j]
// M=i (128/block), N=j (128/block), K=c (512, chunks of 32).
// Register double-buffered global loads.
// ---------------------------------------------------------------------------
__global__ __launch_bounds__(256) void qkv_kernel(const float* __restrict__ x,
                                                  const float* __restrict__ Wp,
                                                  const float* __restrict__ bp) {
    __shared__ unsigned As[32][136];  // [k][m] tf32
    __shared__ unsigned Bs[128][36];  // [n][k] tf32
    int b  = blockIdx.z;
    int i0 = blockIdx.x * 128;
    int j0 = blockIdx.y * 128;
    int tid = threadIdx.x;
    int lane = tid & 31, warp = tid >> 5;
    int wm = warp >> 1, wn = warp & 1;
    int group = lane >> 2, tig = lane & 3;
    const float* xb = x + (size_t)b * CDIM * S_LEN;

    float acc[2][8][4] = {};

    // load-index precompute
    int a_kk = tid >> 3, a_mv = tid & 7;         // A: 32 k-rows x 128 m
    int b_t  = tid & 7,  b_nb = tid >> 3;        // B: 128 n-rows x 32 k

    float4 ra[4], rb[4];
    #pragma unroll
    for (int r = 0; r < 4; r++) {
        ra[r] = *(const float4*)&xb[(size_t)a_kk * S_LEN + i0 + (a_mv + 8 * r) * 4];
        rb[r] = *(const float4*)&Wp[(size_t)(j0 + b_nb + 32 * r) * CDIM + 4 * b_t];
    }

    for (int c0 = 0; c0 < CDIM; c0 += 32) {
        #pragma unroll
        for (int r = 0; r < 4; r++) {
            *(uint4*)&As[a_kk][(a_mv + 8 * r) * 4] = f2tf4(ra[r]);
            *(uint4*)&Bs[b_nb + 32 * r][4 * b_t]   = f2tf4(rb[r]);
        }
        __syncthreads();

        if (c0 + 32 < CDIM) {
            int c1 = c0 + 32;
            #pragma unroll
            for (int r = 0; r < 4; r++) {
                ra[r] = *(const float4*)&xb[(size_t)(c1 + a_kk) * S_LEN + i0 + (a_mv + 8 * r) * 4];
                rb[r] = *(const float4*)&Wp[(size_t)(j0 + b_nb + 32 * r) * CDIM + c1 + 4 * b_t];
            }
        }

        #pragma unroll
        for (int kf = 0; kf < 4; kf++) {
            int k0 = kf * 8;
            unsigned a[2][4], bf[8][2];
            #pragma unroll
            for (int mi = 0; mi < 2; mi++) {
                int m = wm * 32 + mi * 16 + group;
                a[mi][0] = As[k0 + tig][m];
                a[mi][1] = As[k0 + tig][m + 8];
                a[mi][2] = As[k0 + tig + 4][m];
                a[mi][3] = As[k0 + tig + 4][m + 8];
            }
            #pragma unroll
            for (int nf = 0; nf < 8; nf++) {
                int n = wn * 64 + nf * 8 + group;
                bf[nf][0] = Bs[n][k0 + tig];
                bf[nf][1] = Bs[n][k0 + tig + 4];
            }
            #pragma unroll
            for (int mi = 0; mi < 2; mi++)
                #pragma unroll
                for (int nf = 0; nf < 8; nf++)
                    mma_tf32(acc[mi][nf], a[mi], bf[nf], acc[mi][nf]);
        }
        __syncthreads();
    }

    // Epilogue: scatter into g_Q/g_K/g_V, layout [b][h][i][d]
    #pragma unroll
    for (int mi = 0; mi < 2; mi++) {
        int ir = i0 + wm * 32 + mi * 16 + group;
        #pragma unroll
        for (int nf = 0; nf < 8; nf++) {
            int jc = j0 + wn * 64 + nf * 8 + 2 * tig;
            #pragma unroll
            for (int e = 0; e < 4; e++) {
                int i = ir + (e >> 1) * 8;
                int j = jc + (e & 1);
                float v = acc[mi][nf][e] + bp[j];
                int h = j / 192, rem = j - h * 192;
                float* dst = (rem < DK) ? g_Q : (rem < 2 * DK ? g_K : g_V);
                int d = rem & 63;
                dst[(((size_t)b * NH + h) * S_LEN + i) * DK + d] = v;
            }
        }
    }
}

// ---------------------------------------------------------------------------
// Kernel 2: flash attention. Block = (128-query tile, bh). 8 warps x m16.
// Q fragments in registers; K/V staged in smem (register double-buffered);
// P kept in registers, C-frag -> A-frag via quad shuffles.
// ---------------------------------------------------------------------------
__global__ __launch_bounds__(256) void attn_kernel() {
    __shared__ unsigned Ks[64][68];  // [key][d] tf32
    __shared__ unsigned Vs[64][72];  // [key][d] tf32
    int bh = blockIdx.y;
    int i0 = blockIdx.x * 128;
    int tid = threadIdx.x;
    int lane = tid & 31, warp = tid >> 5;
    int group = lane >> 2, tig = lane & 3;
    const float* Qp = g_Q + (size_t)bh * S_LEN * DK;
    const float* Kp = g_K + (size_t)bh * S_LEN * DK;
    const float* Vp = g_V + (size_t)bh * S_LEN * DK;

    // Q fragments (pre-scaled by 1/8), persistent
    unsigned qa[8][4];
    int r0 = i0 + warp * 16 + group, r1 = r0 + 8;
    #pragma unroll
    for (int kf = 0; kf < 8; kf++) {
        int d0 = kf * 8 + tig;
        qa[kf][0] = f2tf(Qp[(size_t)r0 * DK + d0] * 0.125f);
        qa[kf][1] = f2tf(Qp[(size_t)r1 * DK + d0] * 0.125f);
        qa[kf][2] = f2tf(Qp[(size_t)r0 * DK + d0 + 4] * 0.125f);
        qa[kf][3] = f2tf(Qp[(size_t)r1 * DK + d0 + 4] * 0.125f);
    }

    float o[8][4] = {};
    float mrun0 = -1e30f, mrun1 = -1e30f;
    float lrun0 = 0.f, lrun1 = 0.f;

    int l_key = tid >> 4, l_dv = (tid & 15) * 4;
    float4 rk[4], rv[4];
    #pragma unroll
    for (int r = 0; r < 4; r++) {
        int kk = l_key + 16 * r;
        rk[r] = *(const float4*)&Kp[(size_t)kk * DK + l_dv];
        rv[r] = *(const float4*)&Vp[(size_t)kk * DK + l_dv];
    }

    for (int jt = 0; jt < S_LEN; jt += 64) {
        #pragma unroll
        for (int r = 0; r < 4; r++) {
            int kk = l_key + 16 * r;
            *(uint4*)&Ks[kk][l_dv] = f2tf4(rk[r]);
            *(uint4*)&Vs[kk][l_dv] = f2tf4(rv[r]);
        }
        __syncthreads();

        if (jt + 64 < S_LEN) {
            int jn = jt + 64;
            #pragma unroll
            for (int r = 0; r < 4; r++) {
                int kk = l_key + 16 * r;
                rk[r] = *(const float4*)&Kp[(size_t)(jn + kk) * DK + l_dv];
                rv[r] = *(const float4*)&Vp[(size_t)(jn + kk) * DK + l_dv];
            }
        }

        // S = Q K^T : m16 x n64, k=64
        float s[8][4] = {};
        #pragma unroll
        for (int kf = 0; kf < 8; kf++) {
            int k0 = kf * 8;
            #pragma unroll
            for (int nf = 0; nf < 8; nf++) {
                unsigned bf[2];
                bf[0] = Ks[nf * 8 + group][k0 + tig];
                bf[1] = Ks[nf * 8 + group][k0 + tig + 4];
                mma_tf32(s[nf], qa[kf], bf, s[nf]);
            }
        }

        // row max over this key tile
        float mx0 = -1e30f, mx1 = -1e30f;
        #pragma unroll
        for (int nf = 0; nf < 8; nf++) {
            mx0 = fmaxf(mx0, fmaxf(s[nf][0], s[nf][1]));
            mx1 = fmaxf(mx1, fmaxf(s[nf][2], s[nf][3]));
        }
        mx0 = fmaxf(mx0, __shfl_xor_sync(0xffffffffu, mx0, 1));
        mx0 = fmaxf(mx0, __shfl_xor_sync(0xffffffffu, mx0, 2));
        mx1 = fmaxf(mx1, __shfl_xor_sync(0xffffffffu, mx1, 1));
        mx1 = fmaxf(mx1, __shfl_xor_sync(0xffffffffu, mx1, 2));

        float mn0 = fmaxf(mrun0, mx0), mn1 = fmaxf(mrun1, mx1);
        float f0 = exp2f((mrun0 - mn0) * L2E);
        float f1 = exp2f((mrun1 - mn1) * L2E);
        mrun0 = mn0; mrun1 = mn1;
        float ml0 = mn0 * L2E, ml1 = mn1 * L2E;

        // exponentiate (convert to tf32 in place), accumulate denominators
        unsigned p[8][4];
        float sum0 = 0.f, sum1 = 0.f;
        #pragma unroll
        for (int nf = 0; nf < 8; nf++) {
            float p0 = exp2f(fmaf(s[nf][0], L2E, -ml0));
            float p1 = exp2f(fmaf(s[nf][1], L2E, -ml0));
            float p2 = exp2f(fmaf(s[nf][2], L2E, -ml1));
            float p3 = exp2f(fmaf(s[nf][3], L2E, -ml1));
            sum0 += p0 + p1; sum1 += p2 + p3;
            p[nf][0] = f2tf(p0); p[nf][1] = f2tf(p1);
            p[nf][2] = f2tf(p2); p[nf][3] = f2tf(p3);
        }
        sum0 += __shfl_xor_sync(0xffffffffu, sum0, 1);
        sum0 += __shfl_xor_sync(0xffffffffu, sum0, 2);
        sum1 += __shfl_xor_sync(0xffffffffu, sum1, 1);
        sum1 += __shfl_xor_sync(0xffffffffu, sum1, 2);
        lrun0 = lrun0 * f0 + sum0;
        lrun1 = lrun1 * f1 + sum1;

        // rescale O
        #pragma unroll
        for (int nf = 0; nf < 8; nf++) {
            o[nf][0] *= f0; o[nf][1] *= f0;
            o[nf][2] *= f1; o[nf][3] *= f1;
        }

        // O += P V : A-frags built from P C-frags via quad shuffles
        int src1 = (lane & ~3) | (tig >> 1);
        int src2 = src1 + 2;
        bool odd = (tig & 1);
        #pragma unroll
        for (int kf = 0; kf < 8; kf++) {
            unsigned s00 = __shfl_sync(0xffffffffu, p[kf][0], src1);
            unsigned s01 = __shfl_sync(0xffffffffu, p[kf][1], src1);
            unsigned s02 = __shfl_sync(0xffffffffu, p[kf][2], src1);
            unsigned s03 = __shfl_sync(0xffffffffu, p[kf][3], src1);
            unsigned t00 = __shfl_sync(0xffffffffu, p[kf][0], src2);
            unsigned t01 = __shfl_sync(0xffffffffu, p[kf][1], src2);
            unsigned t02 = __shfl_sync(0xffffffffu, p[kf][2], src2);
            unsigned t03 = __shfl_sync(0xffffffffu, p[kf][3], src2);
            unsigned a[4];
            a[0] = odd ? s01 : s00;
            a[1] = odd ? s03 : s02;
            a[2] = odd ? t01 : t00;
            a[3] = odd ? t03 : t02;
            int k0 = kf * 8;
            #pragma unroll
            for (int nf = 0; nf < 8; nf++) {
                unsigned bf[2];
                bf[0] = Vs[k0 + tig][nf * 8 + group];
                bf[1] = Vs[k0 + tig + 4][nf * 8 + group];
                mma_tf32(o[nf], a, bf, o[nf]);
            }
        }
        __syncthreads();
    }

    // Epilogue -> g_res[b][i][h*64+d]
    int b = bh >> 3, h = bh & 7;
    float inv0 = 1.f / lrun0, inv1 = 1.f / lrun1;
    #pragma unroll
    for (int nf = 0; nf < 8; nf++) {
        int d = h * DK + nf * 8 + 2 * tig;
        float2 v0 = make_float2(o[nf][0] * inv0, o[nf][1] * inv0);
        float2 v1 = make_float2(o[nf][2] * inv1, o[nf][3] * inv1);
        *(float2*)&g_res[((size_t)b * S_LEN + r0) * CDIM + d] = v0;
        *(float2*)&g_res[((size_t)b * S_LEN + r1) * CDIM + d] = v1;
    }
}

// ---------------------------------------------------------------------------
// Kernel 3: out[b,c,i] = sum_f res[b,i,f]*Wo[c,f] + bo[c] + x[b,c,i]
// M=c (128/block), N=i (128/block), K=f (512, chunks of 32).
// Register double-buffered global loads.
// ---------------------------------------------------------------------------
__global__ __launch_bounds__(256) void proj_kernel(const float* __restrict__ x,
                                                   const float* __restrict__ Wo,
                                                   const float* __restrict__ bo,
                                                   float* __restrict__ out) {
    __shared__ unsigned As[128][36];  // [c][f] tf32
    __shared__ unsigned Bs[128][36];  // [i][f] tf32
    int b  = blockIdx.z;
    int i0 = blockIdx.x * 128;
    int c0 = blockIdx.y * 128;
    int tid = threadIdx.x;
    int lane = tid & 31, warp = tid >> 5;
    int wm = warp >> 1, wn = warp & 1;
    int group = lane >> 2, tig = lane & 3;
    const float* resb = g_res + (size_t)b * S_LEN * CDIM;

    float acc[2][8][4] = {};

    int l_t = tid & 7, l_rb = tid >> 3;
    float4 rA[4], rB[4];
    #pragma unroll
    for (int r = 0; r < 4; r++) {
        int rr = l_rb + 32 * r;
        rA[r] = *(const float4*)&Wo[(size_t)(c0 + rr) * CDIM + 4 * l_t];
        rB[r] = *(const float4*)&resb[(size_t)(i0 + rr) * CDIM + 4 * l_t];
    }

    for (int f0 = 0; f0 < CDIM; f0 += 32) {
        #pragma unroll
        for (int r = 0; r < 4; r++) {
            int rr = l_rb + 32 * r;
            *(uint4*)&As[rr][4 * l_t] = f2tf4(rA[r]);
            *(uint4*)&Bs[rr][4 * l_t] = f2tf4(rB[r]);
        }
        __syncthreads();

        if (f0 + 32 < CDIM) {
            int f1 = f0 + 32;
            #pragma unroll
            for (int r = 0; r < 4; r++) {
                int rr = l_rb + 32 * r;
                rA[r] = *(const float4*)&Wo[(size_t)(c0 + rr) * CDIM + f1 + 4 * l_t];
                rB[r] = *(const float4*)&resb[(size_t)(i0 + rr) * CDIM + f1 + 4 * l_t];
            }
        }

        #pragma unroll
        for (int kf = 0; kf < 4; kf++) {
            int k0 = kf * 8;
            unsigned a[2][4], bf[8][2];
            #pragma unroll
            for (int mi = 0; mi < 2; mi++) {
                int m = wm * 32 + mi * 16 + group;
                a[mi][0] = As[m][k0 + tig];
                a[mi][1] = As[m + 8][k0 + tig];
                a[mi][2] = As[m][k0 + tig + 4];
                a[mi][3] = As[m + 8][k0 + tig + 4];
            }
            #pragma unroll
            for (int nf = 0; nf < 8; nf++) {
                int n = wn * 64 + nf * 8 + group;
                bf[nf][0] = Bs[n][k0 + tig];
                bf[nf][1] = Bs[n][k0 + tig + 4];
            }
            #pragma unroll
            for (int mi = 0; mi < 2; mi++)
                #pragma unroll
                for (int nf = 0; nf < 8; nf++)
                    mma_tf32(acc[mi][nf], a[mi], bf[nf], acc[mi][nf]);
        }
        __syncthreads();
    }

    // Epilogue: bias + residual, coalesced along i
    #pragma unroll
    for (int mi = 0; mi < 2; mi++) {
        int cr = c0 + wm * 32 + mi * 16 + group;
        #pragma unroll
        for (int nf = 0; nf < 8; nf++) {
            int ic = i0 + wn * 64 + nf * 8 + 2 * tig;
            #pragma unroll
            for (int half = 0; half < 2; half++) {
                int c = cr + half * 8;
                size_t idx = ((size_t)b * CDIM + c) * S_LEN + ic;
                float2 xv = *(const float2*)&x[idx];
                float bias = bo[c];
                float2 ov;
                ov.x = acc[mi][nf][half * 2 + 0] + bias + xv.x;
                ov.y = acc[mi][nf][half * 2 + 1] + bias + xv.y;
                *(float2*)&out[idx] = ov;
            }
        }
    }
}

// ---------------------------------------------------------------------------
extern "C" void kernel_launch(void* const* d_in, const int* in_sizes, int n_in,
                              void* d_out, int out_size) {
    const float* x  = (const float*)d_in[0];
    const float* Wp = (const float*)d_in[1];
    const float* bp = (const float*)d_in[2];
    const float* Wo = (const float*)d_in[3];
    const float* bo = (const float*)d_in[4];
    float* out = (float*)d_out;

    qkv_kernel<<<dim3(S_LEN / 128, 1536 / 128, BDIM), 256>>>(x, Wp, bp);
    attn_kernel<<<dim3(S_LEN / 128, BDIM * NH), 256>>>();
    proj_kernel<<<dim3(S_LEN / 128, CDIM / 128, BDIM), 256>>>(x, Wo, bo, out);
}

// round 4
// speedup vs baseline: 4.4307x; 1.1457x over previous
#include <cuda_runtime.h>

#define S_LEN 1024
#define CDIM 512
#define NH 8
#define DK 64
#define BDIM 4
#define L2E 1.4426950408889634f

// Scratch (static __device__ arrays per harness rules)
__device__ float g_Q[BDIM * NH * S_LEN * DK];
__device__ float g_K[BDIM * NH * S_LEN * DK];
__device__ float g_V[BDIM * NH * S_LEN * DK];
__device__ float g_res[BDIM * S_LEN * CDIM];

// ---------------------------------------------------------------------------
// helpers
// ---------------------------------------------------------------------------
__device__ __forceinline__ unsigned f2tf(float f) {
    unsigned u;
    asm("cvt.rna.tf32.f32 %0, %1;" : "=r"(u) : "f"(f));
    return u;
}
// D = A(16x8) * B(8x8) + C, tf32 inputs, f32 accumulate. d may alias c.
__device__ __forceinline__ void mma_tf32(float* d, const unsigned* a,
                                         const unsigned* b, const float* c) {
    asm volatile(
        "mma.sync.aligned.m16n8k8.row.col.f32.tf32.tf32.f32 "
        "{%0,%1,%2,%3},{%4,%5,%6,%7},{%8,%9},{%10,%11,%12,%13};"
        : "=f"(d[0]), "=f"(d[1]), "=f"(d[2]), "=f"(d[3])
        : "r"(a[0]), "r"(a[1]), "r"(a[2]), "r"(a[3]),
          "r"(b[0]), "r"(b[1]),
          "f"(c[0]), "f"(c[1]), "f"(c[2]), "f"(c[3]));
}
__device__ __forceinline__ void cp16(unsigned dst, const void* src) {
    asm volatile("cp.async.cg.shared.global [%0], [%1], 16;" :: "r"(dst), "l"(src));
}
__device__ __forceinline__ void cp_commit() {
    asm volatile("cp.async.commit_group;");
}
template <int N> __device__ __forceinline__ void cp_wait() {
    asm volatile("cp.async.wait_group %0;" :: "n"(N));
}

// ---------------------------------------------------------------------------
// Kernel 1: QKV projection.  qkv[b,i,j] = sum_c x[b,c,i]*Wp[j,c] + bp[j]
// M=i (128/block), N=j (128/block), K=c (512, 16 chunks of 32).
// 2-stage cp.async pipeline, raw f32 bits used as tf32.
// ---------------------------------------------------------------------------
#define QKV_STG (32 * 136 + 128 * 36)  // words per stage: A[32][136] + B[128][36]

__global__ __launch_bounds__(256, 2) void qkv_kernel(const float* __restrict__ x,
                                                     const float* __restrict__ Wp,
                                                     const float* __restrict__ bp) {
    extern __shared__ unsigned smq[];
    int b  = blockIdx.z;
    int i0 = blockIdx.x * 128;
    int j0 = blockIdx.y * 128;
    int tid = threadIdx.x;
    int lane = tid & 31, warp = tid >> 5;
    int wm = warp >> 1, wn = warp & 1;
    int group = lane >> 2, tig = lane & 3;
    const float* xb = x + (size_t)b * CDIM * S_LEN;

    int a_kk = tid >> 3, a_mv = tid & 7;  // A: 32 k-rows x 128 m, coalesced on m
    int b_t  = tid & 7,  b_nb = tid >> 3; // B: 128 n-rows x 32 k, coalesced on k
    unsigned sbase = (unsigned)__cvta_generic_to_shared(smq);

    float acc[2][8][4] = {};

    auto issue = [&](int c0, int stg) {
        unsigned base = sbase + (unsigned)(stg * QKV_STG) * 4u;
        #pragma unroll
        for (int r = 0; r < 4; r++) {
            cp16(base + (unsigned)(a_kk * 136 + (a_mv + 8 * r) * 4) * 4u,
                 &xb[(size_t)(c0 + a_kk) * S_LEN + i0 + (a_mv + 8 * r) * 4]);
            cp16(base + (unsigned)(32 * 136 + (b_nb + 32 * r) * 36 + 4 * b_t) * 4u,
                 &Wp[(size_t)(j0 + b_nb + 32 * r) * CDIM + c0 + 4 * b_t]);
        }
        cp_commit();
    };

    issue(0, 0);
    issue(32, 1);

    for (int t = 0; t < 16; ++t) {
        if (t == 15) cp_wait<0>(); else cp_wait<1>();
        __syncthreads();
        const unsigned* As = smq + (t & 1) * QKV_STG;   // [32][136]
        const unsigned* Bs = As + 32 * 136;             // [128][36]

        #pragma unroll
        for (int kf = 0; kf < 4; kf++) {
            int k0 = kf * 8;
            unsigned a[2][4], bf[8][2];
            #pragma unroll
            for (int mi = 0; mi < 2; mi++) {
                int m = wm * 32 + mi * 16 + group;
                a[mi][0] = As[(k0 + tig) * 136 + m];
                a[mi][1] = As[(k0 + tig) * 136 + m + 8];
                a[mi][2] = As[(k0 + tig + 4) * 136 + m];
                a[mi][3] = As[(k0 + tig + 4) * 136 + m + 8];
            }
            #pragma unroll
            for (int nf = 0; nf < 8; nf++) {
                int n = wn * 64 + nf * 8 + group;
                bf[nf][0] = Bs[n * 36 + k0 + tig];
                bf[nf][1] = Bs[n * 36 + k0 + tig + 4];
            }
            #pragma unroll
            for (int mi = 0; mi < 2; mi++)
                #pragma unroll
                for (int nf = 0; nf < 8; nf++)
                    mma_tf32(acc[mi][nf], a[mi], bf[nf], acc[mi][nf]);
        }
        __syncthreads();
        if (t + 2 < 16) issue((t + 2) * 32, t & 1);
    }

    // Epilogue: scatter into g_Q/g_K/g_V, layout [b][h][i][d]
    #pragma unroll
    for (int mi = 0; mi < 2; mi++) {
        int ir = i0 + wm * 32 + mi * 16 + group;
        #pragma unroll
        for (int nf = 0; nf < 8; nf++) {
            int jc = j0 + wn * 64 + nf * 8 + 2 * tig;
            #pragma unroll
            for (int e = 0; e < 4; e++) {
                int i = ir + (e >> 1) * 8;
                int j = jc + (e & 1);
                float v = acc[mi][nf][e] + bp[j];
                int h = j / 192, rem = j - h * 192;
                float* dst = (rem < DK) ? g_Q : (rem < 2 * DK ? g_K : g_V);
                int d = rem & 63;
                dst[(((size_t)b * NH + h) * S_LEN + i) * DK + d] = v;
            }
        }
    }
}

// ---------------------------------------------------------------------------
// Kernel 2: flash attention. Block = (128-query tile, bh). 8 warps x m16.
// Q fragments persistent in registers; K/V via 2-stage cp.async pipeline
// (raw f32 bits as tf32); P in registers, C-frag -> A-frag via quad shuffles.
// ---------------------------------------------------------------------------
#define ATTN_STG (64 * 68 + 64 * 72)  // words per stage: K[64][68] + V[64][72]

__global__ __launch_bounds__(256) void attn_kernel() {
    extern __shared__ unsigned sma[];
    int bh = blockIdx.y;
    int i0 = blockIdx.x * 128;
    int tid = threadIdx.x;
    int lane = tid & 31, warp = tid >> 5;
    int group = lane >> 2, tig = lane & 3;
    const float* Qp = g_Q + (size_t)bh * S_LEN * DK;
    const float* Kp = g_K + (size_t)bh * S_LEN * DK;
    const float* Vp = g_V + (size_t)bh * S_LEN * DK;

    int l_key = tid >> 4, l_dv = (tid & 15) * 4;
    unsigned sbase = (unsigned)__cvta_generic_to_shared(sma);

    auto issue = [&](int jt, int stg) {
        unsigned base = sbase + (unsigned)(stg * ATTN_STG) * 4u;
        #pragma unroll
        for (int r = 0; r < 4; r++) {
            int kk = l_key + 16 * r;
            cp16(base + (unsigned)(kk * 68 + l_dv) * 4u,
                 &Kp[(size_t)(jt + kk) * DK + l_dv]);
            cp16(base + (unsigned)(64 * 68 + kk * 72 + l_dv) * 4u,
                 &Vp[(size_t)(jt + kk) * DK + l_dv]);
        }
        cp_commit();
    };

    issue(0, 0);
    issue(64, 1);

    // Q fragments (pre-scaled by 1/8), persistent
    unsigned qa[8][4];
    int r0 = i0 + warp * 16 + group, r1 = r0 + 8;
    #pragma unroll
    for (int kf = 0; kf < 8; kf++) {
        int d0 = kf * 8 + tig;
        qa[kf][0] = f2tf(Qp[(size_t)r0 * DK + d0] * 0.125f);
        qa[kf][1] = f2tf(Qp[(size_t)r1 * DK + d0] * 0.125f);
        qa[kf][2] = f2tf(Qp[(size_t)r0 * DK + d0 + 4] * 0.125f);
        qa[kf][3] = f2tf(Qp[(size_t)r1 * DK + d0 + 4] * 0.125f);
    }

    float o[8][4] = {};
    float mrun0 = -1e30f, mrun1 = -1e30f;
    float lrun0 = 0.f, lrun1 = 0.f;

    for (int t = 0; t < 16; ++t) {
        if (t == 15) cp_wait<0>(); else cp_wait<1>();
        __syncthreads();
        const unsigned* Ks = sma + (t & 1) * ATTN_STG;  // [64][68]
        const unsigned* Vs = Ks + 64 * 68;              // [64][72]

        // S = Q K^T : m16 x n64, k=64
        float s[8][4] = {};
        #pragma unroll
        for (int kf = 0; kf < 8; kf++) {
            int k0 = kf * 8;
            #pragma unroll
            for (int nf = 0; nf < 8; nf++) {
                unsigned bf[2];
                bf[0] = Ks[(nf * 8 + group) * 68 + k0 + tig];
                bf[1] = Ks[(nf * 8 + group) * 68 + k0 + tig + 4];
                mma_tf32(s[nf], qa[kf], bf, s[nf]);
            }
        }

        // row max over this key tile
        float mx0 = -1e30f, mx1 = -1e30f;
        #pragma unroll
        for (int nf = 0; nf < 8; nf++) {
            mx0 = fmaxf(mx0, fmaxf(s[nf][0], s[nf][1]));
            mx1 = fmaxf(mx1, fmaxf(s[nf][2], s[nf][3]));
        }
        mx0 = fmaxf(mx0, __shfl_xor_sync(0xffffffffu, mx0, 1));
        mx0 = fmaxf(mx0, __shfl_xor_sync(0xffffffffu, mx0, 2));
        mx1 = fmaxf(mx1, __shfl_xor_sync(0xffffffffu, mx1, 1));
        mx1 = fmaxf(mx1, __shfl_xor_sync(0xffffffffu, mx1, 2));

        float mn0 = fmaxf(mrun0, mx0), mn1 = fmaxf(mrun1, mx1);
        float f0 = exp2f((mrun0 - mn0) * L2E);
        float f1 = exp2f((mrun1 - mn1) * L2E);
        mrun0 = mn0; mrun1 = mn1;
        float ml0 = mn0 * L2E, ml1 = mn1 * L2E;

        // exponentiate (convert to tf32), accumulate denominators
        unsigned p[8][4];
        float sum0 = 0.f, sum1 = 0.f;
        #pragma unroll
        for (int nf = 0; nf < 8; nf++) {
            float p0 = exp2f(fmaf(s[nf][0], L2E, -ml0));
            float p1 = exp2f(fmaf(s[nf][1], L2E, -ml0));
            float p2 = exp2f(fmaf(s[nf][2], L2E, -ml1));
            float p3 = exp2f(fmaf(s[nf][3], L2E, -ml1));
            sum0 += p0 + p1; sum1 += p2 + p3;
            p[nf][0] = f2tf(p0); p[nf][1] = f2tf(p1);
            p[nf][2] = f2tf(p2); p[nf][3] = f2tf(p3);
        }
        sum0 += __shfl_xor_sync(0xffffffffu, sum0, 1);
        sum0 += __shfl_xor_sync(0xffffffffu, sum0, 2);
        sum1 += __shfl_xor_sync(0xffffffffu, sum1, 1);
        sum1 += __shfl_xor_sync(0xffffffffu, sum1, 2);
        lrun0 = lrun0 * f0 + sum0;
        lrun1 = lrun1 * f1 + sum1;

        // rescale O
        #pragma unroll
        for (int nf = 0; nf < 8; nf++) {
            o[nf][0] *= f0; o[nf][1] *= f0;
            o[nf][2] *= f1; o[nf][3] *= f1;
        }

        // O += P V : A-frags built from P C-frags via quad shuffles
        int src1 = (lane & ~3) | (tig >> 1);
        int src2 = src1 + 2;
        bool odd = (tig & 1);
        #pragma unroll
        for (int kf = 0; kf < 8; kf++) {
            unsigned s00 = __shfl_sync(0xffffffffu, p[kf][0], src1);
            unsigned s01 = __shfl_sync(0xffffffffu, p[kf][1], src1);
            unsigned s02 = __shfl_sync(0xffffffffu, p[kf][2], src1);
            unsigned s03 = __shfl_sync(0xffffffffu, p[kf][3], src1);
            unsigned t00 = __shfl_sync(0xffffffffu, p[kf][0], src2);
            unsigned t01 = __shfl_sync(0xffffffffu, p[kf][1], src2);
            unsigned t02 = __shfl_sync(0xffffffffu, p[kf][2], src2);
            unsigned t03 = __shfl_sync(0xffffffffu, p[kf][3], src2);
            unsigned a[4];
            a[0] = odd ? s01 : s00;
            a[1] = odd ? s03 : s02;
            a[2] = odd ? t01 : t00;
            a[3] = odd ? t03 : t02;
            int k0 = kf * 8;
            #pragma unroll
            for (int nf = 0; nf < 8; nf++) {
                unsigned bf[2];
                bf[0] = Vs[(k0 + tig) * 72 + nf * 8 + group];
                bf[1] = Vs[(k0 + tig + 4) * 72 + nf * 8 + group];
                mma_tf32(o[nf], a, bf, o[nf]);
            }
        }
        __syncthreads();
        if (t + 2 < 16) issue((t + 2) * 64, t & 1);
    }

    // Epilogue -> g_res[b][i][h*64+d]
    int b = bh >> 3, h = bh & 7;
    float inv0 = 1.f / lrun0, inv1 = 1.f / lrun1;
    #pragma unroll
    for (int nf = 0; nf < 8; nf++) {
        int d = h * DK + nf * 8 + 2 * tig;
        float2 v0 = make_float2(o[nf][0] * inv0, o[nf][1] * inv0);
        float2 v1 = make_float2(o[nf][2] * inv1, o[nf][3] * inv1);
        *(float2*)&g_res[((size_t)b * S_LEN + r0) * CDIM + d] = v0;
        *(float2*)&g_res[((size_t)b * S_LEN + r1) * CDIM + d] = v1;
    }
}

// ---------------------------------------------------------------------------
// Kernel 3: out[b,c,i] = sum_f res[b,i,f]*Wo[c,f] + bo[c] + x[b,c,i]
// M=c (128/block), N=i (128/block), K=f (512, 16 chunks of 32).
// 2-stage cp.async pipeline, raw f32 bits as tf32.
// ---------------------------------------------------------------------------
#define PROJ_STG (2 * 128 * 36)  // words per stage: A[128][36] + B[128][36]

__global__ __launch_bounds__(256, 2) void proj_kernel(const float* __restrict__ x,
                                                      const float* __restrict__ Wo,
                                                      const float* __restrict__ bo,
                                                      float* __restrict__ out) {
    extern __shared__ unsigned smp[];
    int b  = blockIdx.z;
    int i0 = blockIdx.x * 128;
    int c0 = blockIdx.y * 128;
    int tid = threadIdx.x;
    int lane = tid & 31, warp = tid >> 5;
    int wm = warp >> 1, wn = warp & 1;
    int group = lane >> 2, tig = lane & 3;
    const float* resb = g_res + (size_t)b * S_LEN * CDIM;

    int l_t = tid & 7, l_rb = tid >> 3;
    unsigned sbase = (unsigned)__cvta_generic_to_shared(smp);

    float acc[2][8][4] = {};

    auto issue = [&](int f0, int stg) {
        unsigned base = sbase + (unsigned)(stg * PROJ_STG) * 4u;
        #pragma unroll
        for (int r = 0; r < 4; r++) {
            int rr = l_rb + 32 * r;
            cp16(base + (unsigned)(rr * 36 + 4 * l_t) * 4u,
                 &Wo[(size_t)(c0 + rr) * CDIM + f0 + 4 * l_t]);
            cp16(base + (unsigned)(128 * 36 + rr * 36 + 4 * l_t) * 4u,
                 &resb[(size_t)(i0 + rr) * CDIM + f0 + 4 * l_t]);
        }
        cp_commit();
    };

    issue(0, 0);
    issue(32, 1);

    for (int t = 0; t < 16; ++t) {
        if (t == 15) cp_wait<0>(); else cp_wait<1>();
        __syncthreads();
        const unsigned* As = smp + (t & 1) * PROJ_STG;  // [128][36] (c rows)
        const unsigned* Bs = As + 128 * 36;             // [128][36] (i rows)

        #pragma unroll
        for (int kf = 0; kf < 4; kf++) {
            int k0 = kf * 8;
            unsigned a[2][4], bf[8][2];
            #pragma unroll
            for (int mi = 0; mi < 2; mi++) {
                int m = wm * 32 + mi * 16 + group;
                a[mi][0] = As[m * 36 + k0 + tig];
                a[mi][1] = As[(m + 8) * 36 + k0 + tig];
                a[mi][2] = As[m * 36 + k0 + tig + 4];
                a[mi][3] = As[(m + 8) * 36 + k0 + tig + 4];
            }
            #pragma unroll
            for (int nf = 0; nf < 8; nf++) {
                int n = wn * 64 + nf * 8 + group;
                bf[nf][0] = Bs[n * 36 + k0 + tig];
                bf[nf][1] = Bs[n * 36 + k0 + tig + 4];
            }
            #pragma unroll
            for (int mi = 0; mi < 2; mi++)
                #pragma unroll
                for (int nf = 0; nf < 8; nf++)
                    mma_tf32(acc[mi][nf], a[mi], bf[nf], acc[mi][nf]);
        }
        __syncthreads();
        if (t + 2 < 16) issue((t + 2) * 32, t & 1);
    }

    // Epilogue: bias + residual, coalesced along i
    #pragma unroll
    for (int mi = 0; mi < 2; mi++) {
        int cr = c0 + wm * 32 + mi * 16 + group;
        #pragma unroll
        for (int nf = 0; nf < 8; nf++) {
            int ic = i0 + wn * 64 + nf * 8 + 2 * tig;
            #pragma unroll
            for (int half = 0; half < 2; half++) {
                int c = cr + half * 8;
                size_t idx = ((size_t)b * CDIM + c) * S_LEN + ic;
                float2 xv = *(const float2*)&x[idx];
                float bias = bo[c];
                float2 ov;
                ov.x = acc[mi][nf][half * 2 + 0] + bias + xv.x;
                ov.y = acc[mi][nf][half * 2 + 1] + bias + xv.y;
                *(float2*)&out[idx] = ov;
            }
        }
    }
}

// ---------------------------------------------------------------------------
extern "C" void kernel_launch(void* const* d_in, const int* in_sizes, int n_in,
                              void* d_out, int out_size) {
    const float* x  = (const float*)d_in[0];
    const float* Wp = (const float*)d_in[1];
    const float* bp = (const float*)d_in[2];
    const float* Wo = (const float*)d_in[3];
    const float* bo = (const float*)d_in[4];
    float* out = (float*)d_out;

    const int qkv_smem  = 2 * QKV_STG  * 4;  // 71680 B
    const int attn_smem = 2 * ATTN_STG * 4;  // 71680 B
    const int proj_smem = 2 * PROJ_STG * 4;  // 73728 B
    cudaFuncSetAttribute(qkv_kernel,  cudaFuncAttributeMaxDynamicSharedMemorySize, qkv_smem);
    cudaFuncSetAttribute(attn_kernel, cudaFuncAttributeMaxDynamicSharedMemorySize, attn_smem);
    cudaFuncSetAttribute(proj_kernel, cudaFuncAttributeMaxDynamicSharedMemorySize, proj_smem);

    qkv_kernel<<<dim3(S_LEN / 128, 1536 / 128, BDIM), 256, qkv_smem>>>(x, Wp, bp);
    attn_kernel<<<dim3(S_LEN / 128, BDIM * NH), 256, attn_smem>>>();
    proj_kernel<<<dim3(S_LEN / 128, CDIM / 128, BDIM), 256, proj_smem>>>(x, Wo, bo, out);
}